// round 9
// baseline (speedup 1.0000x reference)
#include <cuda_runtime.h>
#include <cstdint>

// ---------------------------------------------------------------------------
// Problem constants
// ---------------------------------------------------------------------------
#define NROWS  8192
#define RMINF  5.8f
#define RMAXF  6.0f
#define INV_DR 5.0f
#define SCALE_C 0.00390625f // 4/(128*2*4)

// ---------------------------------------------------------------------------
// Scratch arena: 12,382,720 floats = 47.2 MB (static device memory)
// ---------------------------------------------------------------------------
#define OFF_ACC  ((size_t)0)            // [8192][100]
#define OFF_DRT  ((size_t)819200)       // [8192][400] (reused for dDRt)
#define OFF_T0   ((size_t)4096000)      // [8192][240] t0; later g0
#define OFF_T1   ((size_t)6062080)      // t1
#define OFF_T2   ((size_t)8028160)      // t2
#define OFF_DH1  ((size_t)9994240)      // dh1
#define OFF_W0T  ((size_t)11960320)     // 2 x (240x400)
#define OFF_W1T  ((size_t)12152320)     // 2 x (240x240)
#define OFF_W2T  ((size_t)12267520)     // 2 x (240x240)
#define ARENA_SZ ((size_t)12382720)

__device__ float g_arena[ARENA_SZ];

// ---------------------------------------------------------------------------
// Macro-forced unrolling (literal indices -> guaranteed register promotion)
// ---------------------------------------------------------------------------
#define L25(X) X(0) X(1) X(2) X(3) X(4) X(5) X(6) X(7) X(8) X(9) X(10) X(11) \
  X(12) X(13) X(14) X(15) X(16) X(17) X(18) X(19) X(20) X(21) X(22) X(23) X(24)

// T[e] += h * W[base + e], e = 0..24 (contiguous)
#define AXPY25(T, hval, Wbase) do { const float _h = (hval); const float* _w = (Wbase); \
  T[0]+=_h*_w[0];  T[1]+=_h*_w[1];  T[2]+=_h*_w[2];  T[3]+=_h*_w[3];  T[4]+=_h*_w[4]; \
  T[5]+=_h*_w[5];  T[6]+=_h*_w[6];  T[7]+=_h*_w[7];  T[8]+=_h*_w[8];  T[9]+=_h*_w[9]; \
  T[10]+=_h*_w[10];T[11]+=_h*_w[11];T[12]+=_h*_w[12];T[13]+=_h*_w[13];T[14]+=_h*_w[14]; \
  T[15]+=_h*_w[15];T[16]+=_h*_w[16];T[17]+=_h*_w[17];T[18]+=_h*_w[18];T[19]+=_h*_w[19]; \
  T[20]+=_h*_w[20];T[21]+=_h*_w[21];T[22]+=_h*_w[22];T[23]+=_h*_w[23];T[24]+=_h*_w[24]; } while(0)

// T[j] += h * W[base + j*25], j = 0..24 (stride 25)
#define AXPY25S(T, hval, Wbase) do { const float _h = (hval); const float* _w = (Wbase); \
  T[0]+=_h*_w[0];   T[1]+=_h*_w[25];  T[2]+=_h*_w[50];  T[3]+=_h*_w[75];  T[4]+=_h*_w[100]; \
  T[5]+=_h*_w[125]; T[6]+=_h*_w[150]; T[7]+=_h*_w[175]; T[8]+=_h*_w[200]; T[9]+=_h*_w[225]; \
  T[10]+=_h*_w[250];T[11]+=_h*_w[275];T[12]+=_h*_w[300];T[13]+=_h*_w[325];T[14]+=_h*_w[350]; \
  T[15]+=_h*_w[375];T[16]+=_h*_w[400];T[17]+=_h*_w[425];T[18]+=_h*_w[450];T[19]+=_h*_w[475]; \
  T[20]+=_h*_w[500];T[21]+=_h*_w[525];T[22]+=_h*_w[550];T[23]+=_h*_w[575];T[24]+=_h*_w[600]; } while(0)

// ---------------------------------------------------------------------------
// Embed weight staging layout per pair-type p:
// W0:0 b0:25 W1:50 b1:675 W2:700 b2:1325  total 1350
// ---------------------------------------------------------------------------
__device__ __forceinline__ float embed_w(int p, int off,
    const float* eW0, const float* eb0, const float* eW1,
    const float* eb1, const float* eW2, const float* eb2)
{
    if (off < 25)   return eW0[p*25 + off];
    if (off < 50)   return eb0[p*25 + off - 25];
    if (off < 675)  return eW1[p*625 + off - 50];
    if (off < 700)  return eb1[p*25 + off - 675];
    if (off < 1325) return eW2[p*625 + off - 700];
    return eb2[p*25 + off - 1325];
}

// ---------------------------------------------------------------------------
// Zero Etot + F regions of output
// ---------------------------------------------------------------------------
__global__ void k_zero(float* __restrict__ out) {
    int i = blockIdx.x * blockDim.x + threadIdx.x;
    if (i < 8) out[i] = 0.f;
    if (i < 24576) out[8200 + i] = 0.f;
}

// ---------------------------------------------------------------------------
// Embed forward. One block per atom (256 threads = 256 pairs).
// Inline geometry -> MLP (macro-unrolled) -> acc = blk^T G * scale -> DRt.
// ---------------------------------------------------------------------------
__global__ __launch_bounds__(256) void k_embed_fwd(
    const float* __restrict__ dR_in, const int* __restrict__ neigh_in,
    const float* __restrict__ davg, const float* __restrict__ dstd,
    const float* __restrict__ eW0, const float* __restrict__ eb0,
    const float* __restrict__ eW1, const float* __restrict__ eb1,
    const float* __restrict__ eW2, const float* __restrict__ eb2)
{
    float* __restrict__ acc_out = g_arena + OFF_ACC;
    float* __restrict__ drt_out = g_arena + OFF_DRT;

    __shared__ float Ws[2*1350];
    __shared__ float Gs[256*26];
    __shared__ float Bsm[256*4];
    __shared__ float accS[200];

    int r = blockIdx.x;
    int t = r >> 12;
    int tid = threadIdx.x;

    for (int idx = tid; idx < 2700; idx += 256) {
        int which = idx / 1350, off = idx - which*1350;
        Ws[idx] = embed_w(t*2 + which, off, eW0, eb0, eW1, eb1, eW2, eb2);
    }
    __syncthreads();

    int m = tid;
    const float* W = &Ws[(m >= 128) ? 1350 : 0];

    // ---- inline geometry (all scalars) ----
    int b = (r & 4095) >> 9, nl = r & 511;
    size_t a = (size_t)b * 1024 + t * 512 + nl;
    size_t gsrc = a * 256 + m;
    float dx = dR_in[gsrc*3+0], dy = dR_in[gsrc*3+1], dz = dR_in[gsrc*3+2];
    int ng = neigh_in[gsrc];
    float mf = (ng > 0) ? 1.f : 0.f;
    float dR2 = dx*dx + dy*dy + dz*dz;
    float sdr2 = (ng > 0) ? dR2 : 1.f;
    float Rij = sqrtf(sdr2);
    float inr = mf / Rij;
    float x = Rij * mf;
    float isd = mf / sdr2;
    float u = (x - RMINF) * INV_DR;
    float u2 = u*u, u3 = u2*u;
    float q = -6.f*u2 + 15.f*u - 10.f;
    float poly = u3*q + 1.f;
    bool mid = (x >= RMINF) && (x < RMAXF);
    float vv = ((x < RMINF) ? 1.f : (mid ? poly : 0.f)) * mf;
    size_t sb = (size_t)t*1024 + m*4;
    float bv0 = (inr*vv    - davg[sb+0]) / dstd[sb+0];
    float bv1 = (dx*isd*vv - davg[sb+1]) / dstd[sb+1];
    float bv2 = (dy*isd*vv - davg[sb+2]) / dstd[sb+2];
    float bv3 = (dz*isd*vv - davg[sb+3]) / dstd[sb+3];

    // ---- MLP ----
    float h[25], z[25];
#define S1(E) h[E] = tanhf(bv0*W[E] + W[25+(E)]);
    L25(S1)
#undef S1
#define S2(E) z[E] = W[675+(E)];
    L25(S2)
#undef S2
#define S3(J) AXPY25(z, h[J], &W[50 + (J)*25]);
    L25(S3)
#undef S3
#define S4(E) h[E] = h[E] + tanhf(z[E]);
    L25(S4)
#undef S4
#define S5(E) z[E] = W[1325+(E)];
    L25(S5)
#undef S5
#define S6(J) AXPY25(z, h[J], &W[700 + (J)*25]);
    L25(S6)
#undef S6
#define S7(E) Gs[m*26+(E)] = h[E] + tanhf(z[E]);
    L25(S7)
#undef S7
    Bsm[m*4+0] = bv0; Bsm[m*4+1] = bv1; Bsm[m*4+2] = bv2; Bsm[m*4+3] = bv3;
    __syncthreads();

    // acc[d,e] = sum_k blk[k,d]*G[k,e], split across two halves of threads
    if (tid < 200) {
        int idx = tid % 100, half = tid / 100;
        int d = idx / 25, e = idx - d*25;
        int k0 = half * 128;
        float s0 = 0.f, s1 = 0.f, s2 = 0.f, s3 = 0.f;
        for (int k = k0; k < k0 + 128; k += 4) {
            s0 += Bsm[(k+0)*4+d] * Gs[(k+0)*26+e];
            s1 += Bsm[(k+1)*4+d] * Gs[(k+1)*26+e];
            s2 += Bsm[(k+2)*4+d] * Gs[(k+2)*26+e];
            s3 += Bsm[(k+3)*4+d] * Gs[(k+3)*26+e];
        }
        accS[tid] = (s0+s1)+(s2+s3);
    }
    __syncthreads();
    if (tid < 100) {
        float s = (accS[tid] + accS[tid+100]) * SCALE_C;
        acc_out[(size_t)r*100 + tid] = s;
        accS[tid] = s;
    }
    __syncthreads();
    for (int idx = tid; idx < 400; idx += 256) {
        int e = idx >> 4, f = idx & 15;
        float s = 0.f;
        s += accS[0*25+e] * accS[0*25+f];
        s += accS[1*25+e] * accS[1*25+f];
        s += accS[2*25+e] * accS[2*25+f];
        s += accS[3*25+e] * accS[3*25+f];
        drt_out[(size_t)r*400 + idx] = s;
    }
}

// ---------------------------------------------------------------------------
// Tiled SGEMM with fused A-transforms and epilogues.
// AT: 0 none | 1 A+A2 | 2 A2*(1-A^2) | 3 w3[k]*(1-A^2)
// EP: 0 none | 1 +bias | 2 tanh(+bias) | 3 (acc+Cex)*(1-Cold^2)
// BM=BN=64, BK=16, 256 thr, 4x4 microtile. M mult of 64, K mult of 16.
// ---------------------------------------------------------------------------
template<int AT, int EP>
__global__ __launch_bounds__(256) void sgemm64(
    const float* __restrict__ A, const float* __restrict__ A2,
    const float* __restrict__ w3k, const float* __restrict__ B,
    const float* __restrict__ bias, float* __restrict__ C,
    const float* __restrict__ Cex, int K, int Nc)
{
    __shared__ __align__(16) float As[16][68];
    __shared__ __align__(16) float Bs[16][68];
    int tid = threadIdx.x;
    int tr = tid >> 4, tc = tid & 15;
    int rowBase = blockIdx.y * 64;
    int colBase = blockIdx.x * 64;
    float accv[4][4] = {};

    for (int k0 = 0; k0 < K; k0 += 16) {
        #pragma unroll
        for (int i = 0; i < 4; i++) {
            int l = tid + i*256;
            int mr = l >> 4, kk = l & 15;
            size_t idx = (size_t)(rowBase+mr)*K + k0 + kk;
            float v = A[idx];
            if (AT == 1) v = v + A2[idx];
            else if (AT == 2) v = A2[idx] * (1.f - v*v);
            else if (AT == 3) v = w3k[k0+kk] * (1.f - v*v);
            As[kk][mr] = v;
        }
        #pragma unroll
        for (int i = 0; i < 4; i++) {
            int l = tid + i*256;
            int kr = l >> 6, nc = l & 63;
            int col = colBase + nc;
            Bs[kr][nc] = (col < Nc) ? B[(size_t)(k0+kr)*Nc + col] : 0.f;
        }
        __syncthreads();
        #pragma unroll
        for (int k = 0; k < 16; k++) {
            float4 a4 = *reinterpret_cast<const float4*>(&As[k][tr*4]);
            float4 b4 = *reinterpret_cast<const float4*>(&Bs[k][tc*4]);
            float ar[4] = {a4.x, a4.y, a4.z, a4.w};
            float br[4] = {b4.x, b4.y, b4.z, b4.w};
            #pragma unroll
            for (int i = 0; i < 4; i++)
                #pragma unroll
                for (int j = 0; j < 4; j++) accv[i][j] += ar[i]*br[j];
        }
        __syncthreads();
    }
    #pragma unroll
    for (int i = 0; i < 4; i++) {
        int row = rowBase + tr*4 + i;
        #pragma unroll
        for (int j = 0; j < 4; j++) {
            int col = colBase + tc*4 + j;
            if (col < Nc) {
                size_t idx = (size_t)row*Nc + col;
                float z = accv[i][j];
                if (EP == 1) z += bias[col];
                else if (EP == 2) z = tanhf(z + bias[col]);
                else if (EP == 3) {
                    float old = C[idx];
                    z = (z + Cex[idx]) * (1.f - old*old);
                }
                C[idx] = z;
            }
        }
    }
}

// ---------------------------------------------------------------------------
// Small transpose: out[c*R + r] = in[r*C + c]
// ---------------------------------------------------------------------------
__global__ void k_transpose(const float* __restrict__ in, float* __restrict__ out,
                            int R, int C)
{
    int i = blockIdx.x * blockDim.x + threadIdx.x;
    if (i < R*C) { int r_ = i / C, c = i - r_*C; out[(size_t)c*R + r_] = in[i]; }
}

// ---------------------------------------------------------------------------
// Ei = (t0+t1+t2) . fW3 + fb3 + shift ; write Ei, atomic Etot
// ---------------------------------------------------------------------------
__global__ __launch_bounds__(256) void k_ei(
    const float* __restrict__ fW3, const float* __restrict__ fb3,
    const float* __restrict__ shift, float* __restrict__ out)
{
    const float* t0 = g_arena + OFF_T0;
    const float* t1 = g_arena + OFF_T1;
    const float* t2 = g_arena + OFF_T2;
    int row = blockIdx.x * 8 + (threadIdx.x >> 5);
    int lane = threadIdx.x & 31;
    int t = row >> 12;
    const float* w = fW3 + t*240;
    float s = 0.f;
    for (int c = lane; c < 240; c += 32) {
        size_t i = (size_t)row*240 + c;
        s += (t0[i] + t1[i] + t2[i]) * w[c];
    }
    #pragma unroll
    for (int o = 16; o; o >>= 1) s += __shfl_xor_sync(0xFFFFFFFFu, s, o);
    if (lane == 0) {
        float e = s + fb3[t] + shift[t];
        int b = (row & 4095) >> 9, nl = row & 511;
        out[8 + b*1024 + t*512 + nl] = e;
        atomicAdd(&out[b], e);
    }
}

// ---------------------------------------------------------------------------
// Embed backward + fused dacc + fused pair force.
// Block = (atom r, half). 128 threads, one pair each.
// Register arrays (t0, cur, acc) are macro-indexed only; h1/t2 in smem.
// ---------------------------------------------------------------------------
__global__ __launch_bounds__(128) void k_embed_bwd(
    const float* __restrict__ dR_in, const int* __restrict__ neigh_in,
    const float* __restrict__ davg, const float* __restrict__ dstd,
    const float* __restrict__ eW0, const float* __restrict__ eb0,
    const float* __restrict__ eW1, const float* __restrict__ eb1,
    const float* __restrict__ eW2, const float* __restrict__ eb2,
    float* __restrict__ F)
{
    const float* __restrict__ ddrt = g_arena + OFF_DRT;
    const float* __restrict__ accG = g_arena + OFF_ACC;

    __shared__ float W[1350];
    __shared__ float dac[100];
    __shared__ float hs[128*55];   // per-thread: h1 at [tid*55+e], t2 at [tid*55+27+e]
    __shared__ float red[4][3];

    int blk = blockIdx.x;
    int r = blk >> 1, half = blk & 1;
    int t = r >> 12;
    int p = t*2 + half;
    int tid = threadIdx.x;

    for (int idx = tid; idx < 1350; idx += 128)
        W[idx] = embed_w(p, idx, eW0, eb0, eW1, eb1, eW2, eb2);
    // stage dDRt (400) and acc (100) into the hs region (reused later)
    for (int i = tid; i < 400; i += 128) hs[i] = ddrt[(size_t)r*400 + i];
    if (tid < 100) hs[400 + tid] = accG[(size_t)r*100 + tid];
    __syncthreads();
    if (tid < 100) {
        const float* Gm = hs;
        const float* Am = hs + 400;
        int d = tid / 25, e = tid - d*25;
        float v = 0.f;
        #pragma unroll
        for (int f = 0; f < 16; f++) v += Gm[e*16+f] * Am[d*25+f];
        if (e < 16) {
            float v2 = 0.f;
            #pragma unroll
            for (int e2 = 0; e2 < 25; e2++) v2 += Gm[e2*16+e] * Am[d*25+e2];
            v += v2;
        }
        dac[tid] = SCALE_C * v;
    }
    __syncthreads();

    int m = half*128 + tid;

    // ---- inline geometry (scalars) ----
    int b = (r & 4095) >> 9, nl = r & 511;
    size_t a = (size_t)b * 1024 + t * 512 + nl;
    size_t gsrc = a * 256 + m;
    float dx = dR_in[gsrc*3+0], dy = dR_in[gsrc*3+1], dz = dR_in[gsrc*3+2];
    int ng = neigh_in[gsrc];
    float mf = (ng > 0) ? 1.f : 0.f;
    float dR2 = dx*dx + dy*dy + dz*dz;
    float sdr2 = (ng > 0) ? dR2 : 1.f;
    float Rij = sqrtf(sdr2);
    float inr = mf / Rij;
    float x = Rij * mf;
    float isd = mf / sdr2;
    float inr2 = inr*inr, inr4 = inr2*inr2, inr3 = inr4*x;
    float u = (x - RMINF) * INV_DR;
    float u2 = u*u, u3 = u2*u;
    float q = -6.f*u2 + 15.f*u - 10.f;
    float poly = u3*q + 1.f;
    float dpoly = (3.f*u2*q + u3*(-12.f*u + 15.f)) * INV_DR;
    bool midr = (x >= RMINF) && (x < RMAXF);
    float vv  = ((x < RMINF) ? 1.f : (midr ? poly : 0.f)) * mf;
    float dvv = (midr ? dpoly : 0.f) * mf;
    size_t sb = (size_t)t*1024 + m*4;
    float bv0 = (inr*vv    - davg[sb+0]) / dstd[sb+0];
    float bv1 = (dx*isd*vv - davg[sb+1]) / dstd[sb+1];
    float bv2 = (dy*isd*vv - davg[sb+2]) / dstd[sb+2];
    float bv3 = (dz*isd*vv - davg[sb+3]) / dstd[sb+3];

    float* HS = &hs[tid*55];        // h1[0..24]
    float* TS = &hs[tid*55 + 27];   // t2[0..24]

    float t0[25], cur[25], acc[25];
    // ---- forward recompute ----
#define B1(E) t0[E] = tanhf(bv0*W[E] + W[25+(E)]);
    L25(B1)
#undef B1
#define B2(E) acc[E] = W[675+(E)];
    L25(B2)
#undef B2
#define B3(J) AXPY25(acc, t0[J], &W[50 + (J)*25]);
    L25(B3)
#undef B3
#define B4(E) HS[E] = t0[E] + tanhf(acc[E]);
    L25(B4)
#undef B4
#define B5(E) acc[E] = W[1325+(E)];
    L25(B5)
#undef B5
#define B6(J) AXPY25(acc, HS[J], &W[700 + (J)*25]);
    L25(B6)
#undef B6
#define B7(E) TS[E] = tanhf(acc[E]);
    L25(B7)
#undef B7

    // ---- dblk[d] = sum_e dac[d,e]*(h1[e]+t2[e])  (smem only) ----
    float db0 = 0.f, db1 = 0.f, db2 = 0.f, db3 = 0.f;
    #pragma unroll
    for (int e = 0; e < 25; e++) {
        float G = HS[e] + TS[e];
        db0 += dac[e]*G; db1 += dac[25+e]*G; db2 += dac[50+e]*G; db3 += dac[75+e]*G;
    }

    // ---- dG ----
#define B8(E) cur[E] = dac[E]*bv0 + dac[25+(E)]*bv1 + dac[50+(E)]*bv2 + dac[75+(E)]*bv3;
    L25(B8)
#undef B8

    // ---- dh1 = dG + (dG*(1-t2^2)) @ W2^T ----
#define B9(E) acc[E] = 0.f;
    L25(B9)
#undef B9
#define B10(E) { float tv = TS[E]; AXPY25S(acc, cur[E]*(1.f - tv*tv), &W[700 + (E)]); }
    L25(B10)
#undef B10
#define B11(J) cur[J] += acc[J];
    L25(B11)
#undef B11

    // ---- dh0 = dh1 + (dh1*(1-t1^2)) @ W1^T ;  t1 = h1 - t0 ----
#define B12(E) acc[E] = 0.f;
    L25(B12)
#undef B12
#define B13(E) { float t1e = HS[E] - t0[E]; AXPY25S(acc, cur[E]*(1.f - t1e*t1e), &W[50 + (E)]); }
    L25(B13)
#undef B13
#define B14(J) cur[J] += acc[J];
    L25(B14)
#undef B14

    // ---- ds = sum_e dh0[e]*(1-t0^2)*W0[e] ----
    float ds = 0.f;
#define B15(E) ds += cur[E] * (1.f - t0[E]*t0[E]) * W[E];
    L25(B15)
#undef B15
    db0 += ds;

    // ---- fused pair force ----
    float cm = dvv * inr;
    float comx = cm*dx, comy = cm*dy, comz = cm*dz;
    float s3 = inr3 * vv;
    float dbs0 = db0 * mf / dstd[sb+0];
    float dbs1 = db1 * mf / dstd[sb+1];
    float dbs2 = db2 * mf / dstd[sb+2];
    float dbs3 = db3 * mf / dstd[sb+3];
    float pre0 = inr, pre1 = dx*isd, pre2 = dy*isd, pre3 = dz*isd;

    float px, py, pz_;
    {
        // j = 0 (x)
        float s = dbs0 * (dx*s3 - pre0*comx);
        s += dbs1 * ((2.f*dx*dx*inr4 - inr2) * vv - pre1*comx);
        s += dbs2 * ((2.f*dy*dx*inr4       ) * vv - pre2*comx);
        s += dbs3 * ((2.f*dz*dx*inr4       ) * vv - pre3*comx);
        px = s;
        // j = 1 (y)
        s = dbs0 * (dy*s3 - pre0*comy);
        s += dbs1 * ((2.f*dx*dy*inr4       ) * vv - pre1*comy);
        s += dbs2 * ((2.f*dy*dy*inr4 - inr2) * vv - pre2*comy);
        s += dbs3 * ((2.f*dz*dy*inr4       ) * vv - pre3*comy);
        py = s;
        // j = 2 (z)
        s = dbs0 * (dz*s3 - pre0*comz);
        s += dbs1 * ((2.f*dx*dz*inr4       ) * vv - pre1*comz);
        s += dbs2 * ((2.f*dy*dz*inr4       ) * vv - pre2*comz);
        s += dbs3 * ((2.f*dz*dz*inr4 - inr2) * vv - pre3*comz);
        pz_ = s;
    }

    if (ng > 0) {
        size_t aj = (size_t)b*1024 + (ng - 1);
        atomicAdd(&F[aj*3+0], px);
        atomicAdd(&F[aj*3+1], py);
        atomicAdd(&F[aj*3+2], pz_);
    }

    float sx = px, sy = py, sz = pz_;
    #pragma unroll
    for (int o = 16; o; o >>= 1) {
        sx += __shfl_xor_sync(0xFFFFFFFFu, sx, o);
        sy += __shfl_xor_sync(0xFFFFFFFFu, sy, o);
        sz += __shfl_xor_sync(0xFFFFFFFFu, sz, o);
    }
    int wid = tid >> 5, lane = tid & 31;
    if (lane == 0) { red[wid][0] = sx; red[wid][1] = sy; red[wid][2] = sz; }
    __syncthreads();
    if (tid < 3) {
        float s = red[0][tid] + red[1][tid] + red[2][tid] + red[3][tid];
        atomicAdd(&F[a*3 + tid], -s);
    }
}

// ---------------------------------------------------------------------------
// Launcher
// ---------------------------------------------------------------------------
extern "C" void kernel_launch(void* const* d_in, const int* in_sizes, int n_in,
                              void* d_out, int out_size)
{
    (void)in_sizes; (void)n_in; (void)out_size;
    const float* image_dR   = (const float*)d_in[0];
    const int*   list_neigh = (const int*)  d_in[1];
    const float* davg = (const float*)d_in[2];
    const float* dstd = (const float*)d_in[3];
    const float* eW0 = (const float*)d_in[4];
    const float* eb0 = (const float*)d_in[5];
    const float* eW1 = (const float*)d_in[6];
    const float* eb1 = (const float*)d_in[7];
    const float* eW2 = (const float*)d_in[8];
    const float* eb2 = (const float*)d_in[9];
    const float* fW0 = (const float*)d_in[10];
    const float* fb0 = (const float*)d_in[11];
    const float* fW1 = (const float*)d_in[12];
    const float* fb1 = (const float*)d_in[13];
    const float* fW2 = (const float*)d_in[14];
    const float* fb2 = (const float*)d_in[15];
    const float* fW3 = (const float*)d_in[16];
    const float* fb3 = (const float*)d_in[17];
    const float* eshift = (const float*)d_in[18];
    float* out = (float*)d_out;

    void* arena_v = nullptr;
    cudaGetSymbolAddress(&arena_v, g_arena);
    float* AR = (float*)arena_v;

    float* DRT = AR + OFF_DRT;
    float* T0  = AR + OFF_T0;  float* T1 = AR + OFF_T1;  float* T2 = AR + OFF_T2;
    float* DH1 = AR + OFF_DH1;
    float* W0T = AR + OFF_W0T; float* W1T = AR + OFF_W1T; float* W2T = AR + OFF_W2T;
    float* F   = out + 8200;

    dim3 gN240(4, 64), gN400(7, 64);

    k_zero<<<96, 256>>>(out);
    k_embed_fwd<<<NROWS, 256>>>(image_dR, list_neigh, davg, dstd,
                                eW0, eb0, eW1, eb1, eW2, eb2);

    for (int t = 0; t < 2; t++) {
        k_transpose<<<(96000+255)/256, 256>>>(fW0 + (size_t)t*96000, W0T + (size_t)t*96000, 400, 240);
        k_transpose<<<(57600+255)/256, 256>>>(fW1 + (size_t)t*57600, W1T + (size_t)t*57600, 240, 240);
        k_transpose<<<(57600+255)/256, 256>>>(fW2 + (size_t)t*57600, W2T + (size_t)t*57600, 240, 240);
    }

    // fitting forward: t0, t1, t2
    for (int t = 0; t < 2; t++)
        sgemm64<0,2><<<gN240, 256>>>(DRT + (size_t)t*4096*400, nullptr, nullptr,
                                     fW0 + (size_t)t*96000, fb0 + t*240,
                                     T0 + (size_t)t*4096*240, nullptr, 400, 240);
    for (int t = 0; t < 2; t++)
        sgemm64<0,2><<<gN240, 256>>>(T0 + (size_t)t*4096*240, nullptr, nullptr,
                                     fW1 + (size_t)t*57600, fb1 + t*240,
                                     T1 + (size_t)t*4096*240, nullptr, 240, 240);
    for (int t = 0; t < 2; t++)   // A = t0 + t1
        sgemm64<1,2><<<gN240, 256>>>(T0 + (size_t)t*4096*240, T1 + (size_t)t*4096*240, nullptr,
                                     fW2 + (size_t)t*57600, fb2 + t*240,
                                     T2 + (size_t)t*4096*240, nullptr, 240, 240);
    k_ei<<<NROWS/8, 256>>>(fW3, fb3, eshift, out);

    // fitting backward:
    // DH1 = [fW3*(1-t2^2)] @ W2T + fW3
    for (int t = 0; t < 2; t++)
        sgemm64<3,1><<<gN240, 256>>>(T2 + (size_t)t*4096*240, nullptr, fW3 + t*240,
                                     W2T + (size_t)t*57600, fW3 + t*240,
                                     DH1 + (size_t)t*4096*240, nullptr, 240, 240);
    // T0 <- g0 = ( [DH1*(1-t1^2)] @ W1T + DH1 ) * (1 - t0^2)
    for (int t = 0; t < 2; t++)
        sgemm64<2,3><<<gN240, 256>>>(T1 + (size_t)t*4096*240, DH1 + (size_t)t*4096*240, nullptr,
                                     W1T + (size_t)t*57600, nullptr,
                                     T0 + (size_t)t*4096*240, DH1 + (size_t)t*4096*240, 240, 240);
    // dDRt = g0 @ W0T
    for (int t = 0; t < 2; t++)
        sgemm64<0,0><<<gN400, 256>>>(T0 + (size_t)t*4096*240, nullptr, nullptr,
                                     W0T + (size_t)t*96000, nullptr,
                                     DRT + (size_t)t*4096*400, nullptr, 240, 400);

    k_embed_bwd<<<NROWS*2, 128>>>(image_dR, list_neigh, davg, dstd,
                                  eW0, eb0, eW1, eb1, eW2, eb2, F);
}